// round 10
// baseline (speedup 1.0000x reference)
#include <cuda_runtime.h>
#include <cuda_fp16.h>
#include <math.h>
#include <stdint.h>
#include <string.h>

// ArcFace fused loss. N=512, D=512, C=100000.  INT8 tensor-core path.
//   prep    : per-row symmetric int8 quantization of normalized x and w.
//             g_x8/g_w8 int8, g_sx/g_tw per-row scales (cos = S*T*acc).
//   gemm    : 128x128x512 per CTA, mma.sync.m16n8k32.s8 (int32 acc),
//             4-stage cp.async. Epilogue: v = cos*92.33 - 16 per element
//             (I2F + scale FMA), pack f16x2, ex2.approx.f16x2, fixed frame.
//             Target column patched exactly in fp32 (clip + ArcFace margin),
//             re-injected into the int acc via inverse quantization.
//   finalize: loss_i = log(rowsum_i) + 16*ln2 - tlogit_i; mean -> d_out[0]

#define N_ 512
#define D_ 512
#define C_ 100000
#define CPAD 100096
#define NCHUNK 8              // 512 / 64
#define WBLOCKS 12500         // prep: 8 classes (8 warps) per block

#define CLIP_LO  (-1.0f + 1e-7f)
#define CLIP_HI  (1.0f - 1e-7f)
#define COS_M_   0.8775825618903728f
#define SIN_M_   0.4794255386042030f
#define TH_      (-0.8775825618903728f)
#define MM_      0.2397127693021015f
#define K2F      92.33248261778075f      // 64 / ln(2)
#define SHIFT_LN 11.090354888959125f     // 16 * ln(2)

// smem: 4 stages x (A 128x80B + B 128x80B) + tg + rowacc + sS + sT
#define SA(s)   ((s) * 20480)
#define SB(s)   ((s) * 20480 + 10240)
#define SM_TG   81920
#define SM_ROW  82432
#define SM_SS   82944
#define SM_ST   83456
#define SMEM_BYTES 83968

__device__ signed char g_x8[N_ * D_];
__device__ signed char g_w8[(size_t)CPAD * D_];   // zero-init; pads stay 0
__device__ float g_sx[N_];
__device__ float g_tw[CPAD];                       // zero-init; pads stay 0
__device__ float g_rowsum[N_];
__device__ float g_tlogit[N_];

// ------------------------------------------------------------------ helpers
__device__ __forceinline__ uint32_t smem_u32(const void* p) {
    uint32_t a;
    asm("{ .reg .u64 t; cvta.to.shared.u64 t, %1; cvt.u32.u64 %0, t; }"
        : "=r"(a) : "l"(p));
    return a;
}
__device__ __forceinline__ void cp16(uint32_t dst, const void* src) {
    asm volatile("cp.async.cg.shared.global [%0], [%1], 16;"
                 :: "r"(dst), "l"(src));
}
__device__ __forceinline__ uint32_t lds32(uint32_t a) {
    uint32_t v;
    asm volatile("ld.shared.b32 %0, [%1];" : "=r"(v) : "r"(a));
    return v;
}
__device__ __forceinline__ void imma(int* d, const uint32_t* a, const uint32_t* b) {
    asm volatile(
        "mma.sync.aligned.m16n8k32.row.col.s32.s8.s8.s32 "
        "{%0,%1,%2,%3}, {%4,%5,%6,%7}, {%8,%9}, {%0,%1,%2,%3};"
        : "+r"(d[0]), "+r"(d[1]), "+r"(d[2]), "+r"(d[3])
        : "r"(a[0]), "r"(a[1]), "r"(a[2]), "r"(a[3]), "r"(b[0]), "r"(b[1]));
}
__device__ __forceinline__ uint32_t hadd2(uint32_t a, uint32_t b) {
    uint32_t d; asm("add.rn.f16x2 %0, %1, %2;" : "=r"(d) : "r"(a), "r"(b)); return d;
}
__device__ __forceinline__ uint32_t ex2_h2(uint32_t a) {
    uint32_t d; asm("ex2.approx.f16x2 %0, %1;" : "=r"(d) : "r"(a)); return d;
}
__device__ __forceinline__ uint32_t swap16(uint32_t a) {
    uint32_t d; asm("prmt.b32 %0, %1, %1, 0x1032;" : "=r"(d) : "r"(a)); return d;
}
__device__ __forceinline__ uint32_t pack_h2(float v0, float v1) {
    uint32_t d;
    asm("cvt.rn.f16x2.f32 %0, %1, %2;" : "=r"(d) : "f"(v1), "f"(v0));  // hi, lo
    return d;
}
__device__ __forceinline__ uint32_t pack_s8x4(float a, float b, float c, float d) {
    int i0 = __float2int_rn(a), i1 = __float2int_rn(b);
    int i2 = __float2int_rn(c), i3 = __float2int_rn(d);
    return (uint32_t)((i0 & 255) | ((i1 & 255) << 8) | ((i2 & 255) << 16) | (i3 << 24));
}

// ---------------------------------------------------------------------------
// prep: blocks [0, WBLOCKS): normalize + int8-quantize W (1 warp/class);
//       blocks [WBLOCKS, +256): same for x rows (2 rows/block)
// ---------------------------------------------------------------------------
__global__ void prep_kernel(const float* __restrict__ w,
                            const float* __restrict__ x) {
    int b = blockIdx.x;
    if (b < WBLOCKS) {
        int cls  = b * 8 + (threadIdx.x >> 5);
        int lane = threadIdx.x & 31;
        if (cls >= C_) return;
        const float* p = w + (size_t)cls * D_;
        float4 v[4];
        float ss = 0.0f, am = 0.0f;
        #pragma unroll
        for (int q = 0; q < 4; q++) {
            v[q] = *(const float4*)(p + lane * 4 + q * 128);
            ss += v[q].x * v[q].x + v[q].y * v[q].y + v[q].z * v[q].z + v[q].w * v[q].w;
            am = fmaxf(am, fmaxf(fmaxf(fabsf(v[q].x), fabsf(v[q].y)),
                                 fmaxf(fabsf(v[q].z), fabsf(v[q].w))));
        }
        #pragma unroll
        for (int o = 16; o; o >>= 1) {
            ss += __shfl_xor_sync(0xffffffffu, ss, o);
            am = fmaxf(am, __shfl_xor_sync(0xffffffffu, am, o));
        }
        if (lane == 0) g_tw[cls] = am / (127.0f * sqrtf(ss));
        float k = 127.0f / am;
        uint32_t* dst = (uint32_t*)(g_w8 + (size_t)cls * D_);
        #pragma unroll
        for (int q = 0; q < 4; q++)
            dst[lane + q * 32] = pack_s8x4(v[q].x * k, v[q].y * k, v[q].z * k, v[q].w * k);
    } else {
        int sub = threadIdx.x >> 7;              // two rows per block
        int row = (b - WBLOCKS) * 2 + sub;
        int t   = threadIdx.x & 127;
        if (t == 0) g_rowsum[row] = 0.0f;
        float4 v = *(const float4*)(x + (size_t)row * D_ + t * 4);
        float ss = v.x * v.x + v.y * v.y + v.z * v.z + v.w * v.w;
        float am = fmaxf(fmaxf(fabsf(v.x), fabsf(v.y)), fmaxf(fabsf(v.z), fabsf(v.w)));
        #pragma unroll
        for (int o = 16; o; o >>= 1) {
            ss += __shfl_xor_sync(0xffffffffu, ss, o);
            am = fmaxf(am, __shfl_xor_sync(0xffffffffu, am, o));
        }
        __shared__ float sm[2][4], sa[2][4];
        if ((t & 31) == 0) { sm[sub][t >> 5] = ss; sa[sub][t >> 5] = am; }
        __syncthreads();
        float tot = sm[sub][0] + sm[sub][1] + sm[sub][2] + sm[sub][3];
        float amx = fmaxf(fmaxf(sa[sub][0], sa[sub][1]), fmaxf(sa[sub][2], sa[sub][3]));
        if (t == 0) g_sx[row] = amx / (127.0f * sqrtf(tot));
        float k = 127.0f / amx;
        ((uint32_t*)(g_x8 + (size_t)row * D_))[t] =
            pack_s8x4(v.x * k, v.y * k, v.z * k, v.w * k);
    }
}

// ---------------------------------------------------------------------------
__global__ void __launch_bounds__(256, 2)
arcface_gemm_kernel(const int* __restrict__ target) {
    extern __shared__ __align__(16) char smem[];
    const uint32_t sb = smem_u32(smem);
    int*   tg     = (int*)(smem + SM_TG);
    float* rowacc = (float*)(smem + SM_ROW);
    float* sS     = (float*)(smem + SM_SS);
    float* sT     = (float*)(smem + SM_ST);

    const int tid  = threadIdx.x;
    const int lane = tid & 31;
    const int wid  = tid >> 5;
    const int wm   = wid >> 2;
    const int wn   = wid & 3;
    const int gid  = lane >> 2;
    const int tig  = lane & 3;
    const int row0 = blockIdx.x * 128;   // grid.x = 4
    const int c0   = blockIdx.y * 128;   // grid.y = 782

    if (tid < 128) {
        tg[tid]     = target[row0 + tid];
        rowacc[tid] = 0.0f;
        sS[tid]     = g_sx[row0 + tid];
        sT[tid]     = g_tw[c0 + tid];
    }

    int acc[4][4][4];
    #pragma unroll
    for (int mi = 0; mi < 4; mi++)
        #pragma unroll
        for (int ni = 0; ni < 4; ni++)
            #pragma unroll
            for (int r = 0; r < 4; r++) acc[mi][ni][r] = 0;

    auto load_chunk = [&](int c, int s) {
        const signed char* asrc = g_x8 + (size_t)row0 * D_ + c * 64;
        #pragma unroll
        for (int i = 0; i < 2; i++) {
            int g = i * 256 + tid, row = g >> 2, q = g & 3;
            cp16(sb + SA(s) + row * 80 + q * 16, asrc + (size_t)row * D_ + q * 16);
        }
        const signed char* bsrc = g_w8 + (size_t)c0 * D_ + c * 64;
        #pragma unroll
        for (int i = 0; i < 2; i++) {
            int g = i * 256 + tid, row = g >> 2, q = g & 3;
            cp16(sb + SB(s) + row * 80 + q * 16, bsrc + (size_t)row * D_ + q * 16);
        }
        asm volatile("cp.async.commit_group;" ::: "memory");
    };

    load_chunk(0, 0);
    load_chunk(1, 1);
    load_chunk(2, 2);

    for (int c = 0; c < NCHUNK; c++) {
        const int s = c & 3;
        asm volatile("cp.async.wait_group 2;" ::: "memory");
        __syncthreads();
        if (c + 3 < NCHUNK)
            load_chunk(c + 3, (c + 3) & 3);
        else
            asm volatile("cp.async.commit_group;" ::: "memory");

        const uint32_t A = sb + SA(s);
        const uint32_t B = sb + SB(s);
        #pragma unroll
        for (int kk = 0; kk < 64; kk += 32) {
            uint32_t af[4][4], bf[4][2];
            #pragma unroll
            for (int mi = 0; mi < 4; mi++) {
                uint32_t off = A + (wm * 64 + mi * 16 + gid) * 80 + kk + tig * 4;
                af[mi][0] = lds32(off);
                af[mi][1] = lds32(off + 8 * 80);
                af[mi][2] = lds32(off + 16);
                af[mi][3] = lds32(off + 8 * 80 + 16);
            }
            #pragma unroll
            for (int ni = 0; ni < 4; ni++) {
                uint32_t off = B + (wn * 32 + ni * 8 + gid) * 80 + kk + tig * 4;
                bf[ni][0] = lds32(off);
                bf[ni][1] = lds32(off + 16);
            }
            #pragma unroll
            for (int mi = 0; mi < 4; mi++)
                #pragma unroll
                for (int ni = 0; ni < 4; ni++)
                    imma(acc[mi][ni], af[mi], bf[ni]);
        }
    }

    // ---- epilogue: cos = S*T*acc; v = 92.33*cos - 16; ex2.f16x2 ----------
    float ttr[8];
    #pragma unroll
    for (int ni = 0; ni < 4; ni++) {
        ttr[ni * 2]     = sT[wn * 32 + ni * 8 + 2 * tig];
        ttr[ni * 2 + 1] = sT[wn * 32 + ni * 8 + 2 * tig + 1];
    }

    #pragma unroll
    for (int mi = 0; mi < 4; mi++) {
        #pragma unroll
        for (int h = 0; h < 2; h++) {
            const int r  = wm * 64 + mi * 16 + h * 8 + gid;
            const int gm = row0 + r;
            const float Sr = sS[r];
            const float Kr = Sr * K2F;
            const int lc = tg[r] - c0;

            // exact fp32 target path; re-inject quantized phi into the acc
            if ((unsigned)lc < 128u && (lc >> 5) == wn && ((lc >> 1) & 3) == tig) {
                const int nt = (lc >> 3) & 3, j = lc & 1;
                float ts = ttr[nt * 2 + j];
                float cv = (float)acc[mi][nt][h * 2 + j] * ts * Sr;
                cv = fminf(fmaxf(cv, CLIP_LO), CLIP_HI);
                float t = fminf(fmaxf(1.0f - cv * cv, CLIP_LO), CLIP_HI);
                float phi = cv * COS_M_ - sqrtf(t) * SIN_M_;
                if (!(cv > TH_)) phi = cv - MM_;
                g_tlogit[gm] = phi * 64.0f;
                acc[mi][nt][h * 2 + j] = __float2int_rn(phi / (ts * Sr));
            }

            uint32_t s2 = 0;
            #pragma unroll
            for (int ni = 0; ni < 4; ni++) {
                float f0 = (float)acc[mi][ni][h * 2];
                float f1 = (float)acc[mi][ni][h * 2 + 1];
                float v0 = fmaf(f0 * ttr[ni * 2],     Kr, -16.0f);
                float v1 = fmaf(f1 * ttr[ni * 2 + 1], Kr, -16.0f);
                s2 = hadd2(s2, ex2_h2(pack_h2(v0, v1)));
            }
            s2 = hadd2(s2, swap16(s2));
            __half2 sh; memcpy(&sh, &s2, 4);
            float p = __low2float(sh);
            p += __shfl_xor_sync(0xffffffffu, p, 1);
            p += __shfl_xor_sync(0xffffffffu, p, 2);
            if (tig == 0) atomicAdd(&rowacc[r], p);
        }
    }
    __syncthreads();
    if (tid < 128) atomicAdd(&g_rowsum[row0 + tid], rowacc[tid]);
}

// ---------------------------------------------------------------------------
__global__ void finalize_kernel(float* __restrict__ out) {
    int i = threadIdx.x;   // 512
    float v = logf(g_rowsum[i]) + SHIFT_LN - g_tlogit[i];
    #pragma unroll
    for (int o = 16; o; o >>= 1) v += __shfl_xor_sync(0xffffffffu, v, o);
    __shared__ float sm[16];
    if ((i & 31) == 0) sm[i >> 5] = v;
    __syncthreads();
    if (i < 16) {
        float t = sm[i];
        #pragma unroll
        for (int o = 8; o; o >>= 1) t += __shfl_xor_sync(0x0000ffffu, t, o);
        if (i == 0) out[0] = t * (1.0f / (float)N_);
    }
}

// ---------------------------------------------------------------------------
extern "C" void kernel_launch(void* const* d_in, const int* in_sizes, int n_in,
                              void* d_out, int out_size) {
    const float* x   = (const float*)d_in[0];   // [512, 512] fp32
    const int*   tgt = (const int*)d_in[1];     // [512] int32
    const float* w   = (const float*)d_in[2];   // [100000, 512] fp32

    static int smem_set = 0;
    if (!smem_set) {
        cudaFuncSetAttribute(arcface_gemm_kernel,
                             cudaFuncAttributeMaxDynamicSharedMemorySize, SMEM_BYTES);
        smem_set = 1;
    }

    prep_kernel<<<WBLOCKS + 256, 256>>>(w, x);
    dim3 grid(4, (C_ + 127) / 128);
    arcface_gemm_kernel<<<grid, 256, SMEM_BYTES>>>(tgt);
    finalize_kernel<<<1, N_>>>((float*)d_out);
}